// round 2
// baseline (speedup 1.0000x reference)
#include <cuda_runtime.h>
#include <math.h>

// Problem constants (fixed by reference setup_inputs)
#define BATCH 32
#define SQ 512      // decoder seq len
#define SK 512      // encoder seq len
#define DIM 512
#define DIM2 1024   // 2*DIM, K-dim of final linear
#define SCALE 0.044194173824159216f  // 1/sqrt(512)

// Scratch: attention context (B, SQ, DIM). Device global => no allocation.
__device__ float g_ctx[BATCH * SQ * DIM];

// ---------------------------------------------------------------------------
// Kernel 1: scores S[b,q,k] = SCALE * sum_d Q[b,q,d] * E[b,k,d]   (NT GEMM)
// Tiles: 64x64 output, 16-wide K panels, 256 threads, 4x4 per thread.
// ---------------------------------------------------------------------------
__global__ __launch_bounds__(256) void gemm_scores_nt(
    const float* __restrict__ Q, const float* __restrict__ E,
    float* __restrict__ S)
{
    __shared__ float As[16][64];  // As[k][m]
    __shared__ float Bs[16][64];  // Bs[k][n]

    const int b = blockIdx.z;
    const float* Qb = Q + (size_t)b * SQ * DIM;
    const float* Eb = E + (size_t)b * SK * DIM;
    float* Sb = S + (size_t)b * SQ * SK;

    const int mBase = blockIdx.y * 64;
    const int nBase = blockIdx.x * 64;
    const int tid = threadIdx.x;
    const int ty = tid >> 4;        // 0..15
    const int tx = tid & 15;        // 0..15
    const int loadRow = tid >> 2;   // 0..63
    const int loadCol = (tid & 3) * 4;

    float acc[4][4] = {};

    for (int k0 = 0; k0 < DIM; k0 += 16) {
        float4 qa = *(const float4*)(Qb + (size_t)(mBase + loadRow) * DIM + k0 + loadCol);
        float4 eb = *(const float4*)(Eb + (size_t)(nBase + loadRow) * DIM + k0 + loadCol);
        __syncthreads();
        As[loadCol + 0][loadRow] = qa.x; As[loadCol + 1][loadRow] = qa.y;
        As[loadCol + 2][loadRow] = qa.z; As[loadCol + 3][loadRow] = qa.w;
        Bs[loadCol + 0][loadRow] = eb.x; Bs[loadCol + 1][loadRow] = eb.y;
        Bs[loadCol + 2][loadRow] = eb.z; Bs[loadCol + 3][loadRow] = eb.w;
        __syncthreads();
        #pragma unroll
        for (int k = 0; k < 16; k++) {
            float a[4], bb[4];
            #pragma unroll
            for (int i = 0; i < 4; i++) a[i] = As[k][ty * 4 + i];
            #pragma unroll
            for (int j = 0; j < 4; j++) bb[j] = Bs[k][tx * 4 + j];
            #pragma unroll
            for (int i = 0; i < 4; i++)
                #pragma unroll
                for (int j = 0; j < 4; j++)
                    acc[i][j] = fmaf(a[i], bb[j], acc[i][j]);
        }
    }

    #pragma unroll
    for (int i = 0; i < 4; i++) {
        int m = mBase + ty * 4 + i;
        float4 v;
        v.x = acc[i][0] * SCALE; v.y = acc[i][1] * SCALE;
        v.z = acc[i][2] * SCALE; v.w = acc[i][3] * SCALE;
        *(float4*)(Sb + (size_t)m * SK + nBase + tx * 4) = v;
    }
}

// ---------------------------------------------------------------------------
// Kernel 2: in-place row softmax over SK=512 columns. One block per row.
// ---------------------------------------------------------------------------
__global__ __launch_bounds__(256) void softmax_rows(float* __restrict__ S)
{
    const int row = blockIdx.x;                // 0 .. BATCH*SQ-1
    float* p = S + (size_t)row * SK;
    const int tid = threadIdx.x;

    float v0 = p[tid];
    float v1 = p[tid + 256];

    __shared__ float red[8];

    // max reduce
    float m = fmaxf(v0, v1);
    #pragma unroll
    for (int o = 16; o > 0; o >>= 1) m = fmaxf(m, __shfl_xor_sync(0xffffffffu, m, o));
    if ((tid & 31) == 0) red[tid >> 5] = m;
    __syncthreads();
    m = red[0];
    #pragma unroll
    for (int i = 1; i < 8; i++) m = fmaxf(m, red[i]);

    float e0 = __expf(v0 - m);
    float e1 = __expf(v1 - m);

    // sum reduce
    float s = e0 + e1;
    #pragma unroll
    for (int o = 16; o > 0; o >>= 1) s += __shfl_xor_sync(0xffffffffu, s, o);
    __syncthreads();
    if ((tid & 31) == 0) red[tid >> 5] = s;
    __syncthreads();
    s = red[0];
    #pragma unroll
    for (int i = 1; i < 8; i++) s += red[i];

    float inv = 1.0f / s;
    p[tid] = e0 * inv;
    p[tid + 256] = e1 * inv;
}

// ---------------------------------------------------------------------------
// Kernel 3: context C[b,q,d] = sum_k A[b,q,k] * E[b,k,d]   (NN GEMM)
// ---------------------------------------------------------------------------
__global__ __launch_bounds__(256) void gemm_ctx_nn(
    const float* __restrict__ A, const float* __restrict__ E,
    float* __restrict__ C)
{
    __shared__ float As[16][64];  // As[k][m]
    __shared__ float Bs[16][64];  // Bs[k][n]

    const int b = blockIdx.z;
    const float* Ab = A + (size_t)b * SQ * SK;
    const float* Eb = E + (size_t)b * SK * DIM;
    float* Cb = C + (size_t)b * SQ * DIM;

    const int mBase = blockIdx.y * 64;
    const int nBase = blockIdx.x * 64;
    const int tid = threadIdx.x;
    const int ty = tid >> 4;
    const int tx = tid & 15;
    const int loadRowA = tid >> 2;       // 0..63 (m)
    const int loadColA = (tid & 3) * 4;  // k
    const int loadRowB = tid >> 4;       // 0..15 (k)
    const int loadColB = (tid & 15) * 4; // n

    float acc[4][4] = {};

    for (int k0 = 0; k0 < SK; k0 += 16) {
        float4 aa = *(const float4*)(Ab + (size_t)(mBase + loadRowA) * SK + k0 + loadColA);
        float4 bb4 = *(const float4*)(Eb + (size_t)(k0 + loadRowB) * DIM + nBase + loadColB);
        __syncthreads();
        As[loadColA + 0][loadRowA] = aa.x; As[loadColA + 1][loadRowA] = aa.y;
        As[loadColA + 2][loadRowA] = aa.z; As[loadColA + 3][loadRowA] = aa.w;
        *(float4*)&Bs[loadRowB][loadColB] = bb4;
        __syncthreads();
        #pragma unroll
        for (int k = 0; k < 16; k++) {
            float a[4], bb[4];
            #pragma unroll
            for (int i = 0; i < 4; i++) a[i] = As[k][ty * 4 + i];
            #pragma unroll
            for (int j = 0; j < 4; j++) bb[j] = Bs[k][tx * 4 + j];
            #pragma unroll
            for (int i = 0; i < 4; i++)
                #pragma unroll
                for (int j = 0; j < 4; j++)
                    acc[i][j] = fmaf(a[i], bb[j], acc[i][j]);
        }
    }

    #pragma unroll
    for (int i = 0; i < 4; i++) {
        int m = mBase + ty * 4 + i;
        float4 v = make_float4(acc[i][0], acc[i][1], acc[i][2], acc[i][3]);
        *(float4*)(Cb + (size_t)m * DIM + nBase + tx * 4) = v;
    }
}

// ---------------------------------------------------------------------------
// Kernel 4: out[b,q,n] = tanh( sum_j cat[b,q,j]*W[n,j] + bias[n] ) * mask[b,q]
// cat[b,q,j] = Q[b,q,j] (j<512) else ctx[b,q,j-512]. W row-major (512,1024). NT.
// ---------------------------------------------------------------------------
__global__ __launch_bounds__(256) void gemm_out_nt(
    const float* __restrict__ Q, const float* __restrict__ W,
    const float* __restrict__ bias, const float* __restrict__ mask,
    float* __restrict__ O)
{
    __shared__ float As[16][64];  // As[k][m]
    __shared__ float Bs[16][64];  // Bs[k][n]

    const int b = blockIdx.z;
    const float* Qb = Q + (size_t)b * SQ * DIM;
    const float* Cb = g_ctx + (size_t)b * SQ * DIM;
    float* Ob = O + (size_t)b * SQ * DIM;

    const int mBase = blockIdx.y * 64;
    const int nBase = blockIdx.x * 64;
    const int tid = threadIdx.x;
    const int ty = tid >> 4;
    const int tx = tid & 15;
    const int loadRow = tid >> 2;
    const int loadCol = (tid & 3) * 4;

    float acc[4][4] = {};

    for (int k0 = 0; k0 < DIM2; k0 += 16) {
        const float* Asrc = (k0 < DIM) ? Qb : Cb;
        int kk = k0 & (DIM - 1);  // k0 mod 512
        float4 aa = *(const float4*)(Asrc + (size_t)(mBase + loadRow) * DIM + kk + loadCol);
        float4 wb = *(const float4*)(W + (size_t)(nBase + loadRow) * DIM2 + k0 + loadCol);
        __syncthreads();
        As[loadCol + 0][loadRow] = aa.x; As[loadCol + 1][loadRow] = aa.y;
        As[loadCol + 2][loadRow] = aa.z; As[loadCol + 3][loadRow] = aa.w;
        Bs[loadCol + 0][loadRow] = wb.x; Bs[loadCol + 1][loadRow] = wb.y;
        Bs[loadCol + 2][loadRow] = wb.z; Bs[loadCol + 3][loadRow] = wb.w;
        __syncthreads();
        #pragma unroll
        for (int k = 0; k < 16; k++) {
            float a[4], bb[4];
            #pragma unroll
            for (int i = 0; i < 4; i++) a[i] = As[k][ty * 4 + i];
            #pragma unroll
            for (int j = 0; j < 4; j++) bb[j] = Bs[k][tx * 4 + j];
            #pragma unroll
            for (int i = 0; i < 4; i++)
                #pragma unroll
                for (int j = 0; j < 4; j++)
                    acc[i][j] = fmaf(a[i], bb[j], acc[i][j]);
        }
    }

    const int n0 = nBase + tx * 4;
    float b0 = bias[n0 + 0], b1 = bias[n0 + 1], b2 = bias[n0 + 2], b3 = bias[n0 + 3];
    #pragma unroll
    for (int i = 0; i < 4; i++) {
        int m = mBase + ty * 4 + i;
        float mk = mask[(size_t)b * SQ + m];
        float4 v;
        v.x = tanhf(acc[i][0] + b0) * mk;
        v.y = tanhf(acc[i][1] + b1) * mk;
        v.z = tanhf(acc[i][2] + b2) * mk;
        v.w = tanhf(acc[i][3] + b3) * mk;
        *(float4*)(Ob + (size_t)m * DIM + n0) = v;
    }
}

// ---------------------------------------------------------------------------
extern "C" void kernel_launch(void* const* d_in, const int* in_sizes, int n_in,
                              void* d_out, int out_size)
{
    const float* Q    = (const float*)d_in[0];  // padded_seqs   (32,512,512)
    const float* E    = (const float*)d_in[1];  // encoder seqs  (32,512,512)
    const float* mask = (const float*)d_in[2];  // decoder_mask  (32,512,1)
    const float* W    = (const float*)d_in[3];  // (512,1024)
    const float* bias = (const float*)d_in[4];  // (512,)

    float* out = (float*)d_out;
    float* out_masked  = out;                               // (32,512,512)
    float* out_weights = out + (size_t)BATCH * SQ * DIM;    // (32,512,512)

    float* ctx;
    cudaGetSymbolAddress((void**)&ctx, g_ctx);

    dim3 grid_g(SK / 64, SQ / 64, BATCH);   // (8,8,32)
    dim3 blk(256);

    // 1) scores (scaled) -> weights buffer (pre-softmax scratch lives in output)
    gemm_scores_nt<<<grid_g, blk>>>(Q, E, out_weights);
    // 2) softmax in-place
    softmax_rows<<<BATCH * SQ, 256>>>(out_weights);
    // 3) context = weights @ E
    dim3 grid_c(DIM / 64, SQ / 64, BATCH);
    gemm_ctx_nn<<<grid_c, blk>>>(out_weights, E, ctx);
    // 4) out = tanh([Q, ctx] @ W^T + b) * mask
    dim3 grid_o(DIM / 64, SQ / 64, BATCH);
    gemm_out_nt<<<grid_o, blk>>>(Q, W, bias, mask, out_masked);
}

// round 3
// speedup vs baseline: 3.1709x; 3.1709x over previous
#include <cuda_runtime.h>
#include <math.h>
#include <stdint.h>

// Problem constants (fixed by reference setup_inputs)
#define BATCH 32
#define SQ 512
#define SK 512
#define DIM 512
#define DIM2 1024
#define SCALE 0.044194173824159216f  // 1/sqrt(512)

// Tiling
#define BM 128
#define BN 128
#define BK 32
#define AS_STRIDE 36    // [m][k] pad 4 words
#define BS_STRIDE 36    // NT: [n][k] pad 4 words
#define BS_STRIDE_NN 136 // NN: [k][n] pad 8 words (conflict-free for 4k+n pattern)

// Scratch: attention context (B, SQ, DIM). Device global => no allocation.
__device__ float g_ctx[BATCH * SQ * DIM];

__device__ __forceinline__ uint32_t f2tf32(float f) {
    uint32_t r;
    asm("cvt.rna.tf32.f32 %0, %1;" : "=r"(r) : "f"(f));
    return r;
}

__device__ __forceinline__ void mma_tf32(float c[4],
    uint32_t a0, uint32_t a1, uint32_t a2, uint32_t a3,
    uint32_t b0, uint32_t b1)
{
    asm volatile(
        "mma.sync.aligned.m16n8k8.row.col.f32.tf32.tf32.f32 "
        "{%0,%1,%2,%3}, {%4,%5,%6,%7}, {%8,%9}, {%0,%1,%2,%3};"
        : "+f"(c[0]), "+f"(c[1]), "+f"(c[2]), "+f"(c[3])
        : "r"(a0), "r"(a1), "r"(a2), "r"(a3), "r"(b0), "r"(b1));
}

// ---------------------------------------------------------------------------
// Kernel 1: scores S[b,q,k] = SCALE * Q[b,q,:] . E[b,k,:]   (NT, K=512)
// ---------------------------------------------------------------------------
__global__ __launch_bounds__(256, 1) void gemm_scores_tc(
    const float* __restrict__ Q, const float* __restrict__ E,
    float* __restrict__ S)
{
    __shared__ uint32_t As[BM * AS_STRIDE];
    __shared__ uint32_t Bs[BN * BS_STRIDE];

    const int b = blockIdx.z;
    const float* Qb = Q + (size_t)b * SQ * DIM;
    const float* Eb = E + (size_t)b * SK * DIM;
    float* Sb = S + (size_t)b * SQ * SK;

    const int mBase = blockIdx.y * BM;
    const int nBase = blockIdx.x * BN;
    const int tid = threadIdx.x;
    const int lane = tid & 31;
    const int w = tid >> 5;
    const int m0 = (w & 3) * 32;
    const int n0 = (w >> 2) * 64;

    float acc[2][8][4];
    #pragma unroll
    for (int i = 0; i < 2; i++)
        #pragma unroll
        for (int j = 0; j < 8; j++)
            #pragma unroll
            for (int q = 0; q < 4; q++) acc[i][j][q] = 0.f;

    const int ldRow = tid >> 3;         // 0..31 (x4 passes -> 128 rows)
    const int ldCol = (tid & 7) * 4;    // k offset within panel

    float4 stA[4], stB[4];
    // preload panel 0
    #pragma unroll
    for (int p = 0; p < 4; p++) {
        int row = ldRow + p * 32;
        stA[p] = *(const float4*)(Qb + (size_t)(mBase + row) * DIM + ldCol);
        stB[p] = *(const float4*)(Eb + (size_t)(nBase + row) * DIM + ldCol);
    }

    for (int k0 = 0; k0 < DIM; k0 += BK) {
        // commit staged panel to smem (with tf32 convert)
        #pragma unroll
        for (int p = 0; p < 4; p++) {
            int row = ldRow + p * 32;
            uint32_t* pa = &As[row * AS_STRIDE + ldCol];
            pa[0] = f2tf32(stA[p].x); pa[1] = f2tf32(stA[p].y);
            pa[2] = f2tf32(stA[p].z); pa[3] = f2tf32(stA[p].w);
            uint32_t* pb = &Bs[row * BS_STRIDE + ldCol];
            pb[0] = f2tf32(stB[p].x); pb[1] = f2tf32(stB[p].y);
            pb[2] = f2tf32(stB[p].z); pb[3] = f2tf32(stB[p].w);
        }
        __syncthreads();

        // prefetch next panel while computing
        if (k0 + BK < DIM) {
            #pragma unroll
            for (int p = 0; p < 4; p++) {
                int row = ldRow + p * 32;
                stA[p] = *(const float4*)(Qb + (size_t)(mBase + row) * DIM + k0 + BK + ldCol);
                stB[p] = *(const float4*)(Eb + (size_t)(nBase + row) * DIM + k0 + BK + ldCol);
            }
        }

        #pragma unroll
        for (int kc = 0; kc < BK; kc += 8) {
            uint32_t af[2][4], bf[8][2];
            #pragma unroll
            for (int mi = 0; mi < 2; mi++) {
                int r = m0 + mi * 16 + (lane >> 2);
                int c = kc + (lane & 3);
                af[mi][0] = As[r * AS_STRIDE + c];
                af[mi][1] = As[(r + 8) * AS_STRIDE + c];
                af[mi][2] = As[r * AS_STRIDE + c + 4];
                af[mi][3] = As[(r + 8) * AS_STRIDE + c + 4];
            }
            #pragma unroll
            for (int nj = 0; nj < 8; nj++) {
                int r = n0 + nj * 8 + (lane >> 2);
                int c = kc + (lane & 3);
                bf[nj][0] = Bs[r * BS_STRIDE + c];
                bf[nj][1] = Bs[r * BS_STRIDE + c + 4];
            }
            #pragma unroll
            for (int mi = 0; mi < 2; mi++)
                #pragma unroll
                for (int nj = 0; nj < 8; nj++)
                    mma_tf32(acc[mi][nj], af[mi][0], af[mi][1], af[mi][2], af[mi][3],
                             bf[nj][0], bf[nj][1]);
        }
        __syncthreads();
    }

    // epilogue: scale + store
    #pragma unroll
    for (int mi = 0; mi < 2; mi++) {
        #pragma unroll
        for (int nj = 0; nj < 8; nj++) {
            int row = mBase + m0 + mi * 16 + (lane >> 2);
            int col = nBase + n0 + nj * 8 + (lane & 3) * 2;
            float2 v0 = make_float2(acc[mi][nj][0] * SCALE, acc[mi][nj][1] * SCALE);
            float2 v1 = make_float2(acc[mi][nj][2] * SCALE, acc[mi][nj][3] * SCALE);
            *(float2*)(Sb + (size_t)row * SK + col) = v0;
            *(float2*)(Sb + (size_t)(row + 8) * SK + col) = v1;
        }
    }
}

// ---------------------------------------------------------------------------
// Kernel 2: in-place row softmax over SK=512 columns.
// ---------------------------------------------------------------------------
__global__ __launch_bounds__(256) void softmax_rows(float* __restrict__ S)
{
    const int row = blockIdx.x;
    float* p = S + (size_t)row * SK;
    const int tid = threadIdx.x;

    float v0 = p[tid];
    float v1 = p[tid + 256];

    __shared__ float red[8];

    float m = fmaxf(v0, v1);
    #pragma unroll
    for (int o = 16; o > 0; o >>= 1) m = fmaxf(m, __shfl_xor_sync(0xffffffffu, m, o));
    if ((tid & 31) == 0) red[tid >> 5] = m;
    __syncthreads();
    m = red[0];
    #pragma unroll
    for (int i = 1; i < 8; i++) m = fmaxf(m, red[i]);

    float e0 = __expf(v0 - m);
    float e1 = __expf(v1 - m);

    float s = e0 + e1;
    #pragma unroll
    for (int o = 16; o > 0; o >>= 1) s += __shfl_xor_sync(0xffffffffu, s, o);
    __syncthreads();
    if ((tid & 31) == 0) red[tid >> 5] = s;
    __syncthreads();
    s = red[0];
    #pragma unroll
    for (int i = 1; i < 8; i++) s += red[i];

    float inv = 1.0f / s;
    p[tid] = e0 * inv;
    p[tid + 256] = e1 * inv;
}

// ---------------------------------------------------------------------------
// Kernel 3: context C[b,q,d] = sum_k A[b,q,k] * E[b,k,d]   (NN, K=512)
// ---------------------------------------------------------------------------
__global__ __launch_bounds__(256, 1) void gemm_ctx_tc(
    const float* __restrict__ A, const float* __restrict__ E,
    float* __restrict__ C)
{
    __shared__ uint32_t As[BM * AS_STRIDE];        // [m][k]
    __shared__ uint32_t Bs[BK * BS_STRIDE_NN];     // [k][n]

    const int b = blockIdx.z;
    const float* Ab = A + (size_t)b * SQ * SK;
    const float* Eb = E + (size_t)b * SK * DIM;
    float* Cb = C + (size_t)b * SQ * DIM;

    const int mBase = blockIdx.y * BM;
    const int nBase = blockIdx.x * BN;
    const int tid = threadIdx.x;
    const int lane = tid & 31;
    const int w = tid >> 5;
    const int m0 = (w & 3) * 32;
    const int n0 = (w >> 2) * 64;

    float acc[2][8][4];
    #pragma unroll
    for (int i = 0; i < 2; i++)
        #pragma unroll
        for (int j = 0; j < 8; j++)
            #pragma unroll
            for (int q = 0; q < 4; q++) acc[i][j][q] = 0.f;

    const int ldRowA = tid >> 3;        // A: 0..31 x4
    const int ldColA = (tid & 7) * 4;
    const int ldRowB = tid >> 5;        // B: k row 0..7 x4
    const int ldColB = (tid & 31) * 4;  // n col

    float4 stA[4], stB[4];
    #pragma unroll
    for (int p = 0; p < 4; p++) {
        stA[p] = *(const float4*)(Ab + (size_t)(mBase + ldRowA + p * 32) * SK + ldColA);
        stB[p] = *(const float4*)(Eb + (size_t)(ldRowB + p * 8) * DIM + nBase + ldColB);
    }

    for (int k0 = 0; k0 < SK; k0 += BK) {
        #pragma unroll
        for (int p = 0; p < 4; p++) {
            uint32_t* pa = &As[(ldRowA + p * 32) * AS_STRIDE + ldColA];
            pa[0] = f2tf32(stA[p].x); pa[1] = f2tf32(stA[p].y);
            pa[2] = f2tf32(stA[p].z); pa[3] = f2tf32(stA[p].w);
            uint32_t* pb = &Bs[(ldRowB + p * 8) * BS_STRIDE_NN + ldColB];
            pb[0] = f2tf32(stB[p].x); pb[1] = f2tf32(stB[p].y);
            pb[2] = f2tf32(stB[p].z); pb[3] = f2tf32(stB[p].w);
        }
        __syncthreads();

        if (k0 + BK < SK) {
            #pragma unroll
            for (int p = 0; p < 4; p++) {
                stA[p] = *(const float4*)(Ab + (size_t)(mBase + ldRowA + p * 32) * SK + k0 + BK + ldColA);
                stB[p] = *(const float4*)(Eb + (size_t)(k0 + BK + ldRowB + p * 8) * DIM + nBase + ldColB);
            }
        }

        #pragma unroll
        for (int kc = 0; kc < BK; kc += 8) {
            uint32_t af[2][4], bf[8][2];
            #pragma unroll
            for (int mi = 0; mi < 2; mi++) {
                int r = m0 + mi * 16 + (lane >> 2);
                int c = kc + (lane & 3);
                af[mi][0] = As[r * AS_STRIDE + c];
                af[mi][1] = As[(r + 8) * AS_STRIDE + c];
                af[mi][2] = As[r * AS_STRIDE + c + 4];
                af[mi][3] = As[(r + 8) * AS_STRIDE + c + 4];
            }
            #pragma unroll
            for (int nj = 0; nj < 8; nj++) {
                int n = n0 + nj * 8 + (lane >> 2);
                int k = kc + (lane & 3);
                bf[nj][0] = Bs[k * BS_STRIDE_NN + n];
                bf[nj][1] = Bs[(k + 4) * BS_STRIDE_NN + n];
            }
            #pragma unroll
            for (int mi = 0; mi < 2; mi++)
                #pragma unroll
                for (int nj = 0; nj < 8; nj++)
                    mma_tf32(acc[mi][nj], af[mi][0], af[mi][1], af[mi][2], af[mi][3],
                             bf[nj][0], bf[nj][1]);
        }
        __syncthreads();
    }

    #pragma unroll
    for (int mi = 0; mi < 2; mi++) {
        #pragma unroll
        for (int nj = 0; nj < 8; nj++) {
            int row = mBase + m0 + mi * 16 + (lane >> 2);
            int col = nBase + n0 + nj * 8 + (lane & 3) * 2;
            *(float2*)(Cb + (size_t)row * DIM + col) = make_float2(acc[mi][nj][0], acc[mi][nj][1]);
            *(float2*)(Cb + (size_t)(row + 8) * DIM + col) = make_float2(acc[mi][nj][2], acc[mi][nj][3]);
        }
    }
}

// ---------------------------------------------------------------------------
// Kernel 4: out = tanh([Q,ctx] @ W^T + b) * mask   (NT, K=1024)
// ---------------------------------------------------------------------------
__global__ __launch_bounds__(256, 1) void gemm_out_tc(
    const float* __restrict__ Q, const float* __restrict__ W,
    const float* __restrict__ bias, const float* __restrict__ mask,
    float* __restrict__ O)
{
    __shared__ uint32_t As[BM * AS_STRIDE];
    __shared__ uint32_t Bs[BN * BS_STRIDE];

    const int b = blockIdx.z;
    const float* Qb = Q + (size_t)b * SQ * DIM;
    const float* Cb = g_ctx + (size_t)b * SQ * DIM;
    float* Ob = O + (size_t)b * SQ * DIM;

    const int mBase = blockIdx.y * BM;
    const int nBase = blockIdx.x * BN;
    const int tid = threadIdx.x;
    const int lane = tid & 31;
    const int w = tid >> 5;
    const int m0 = (w & 3) * 32;
    const int n0 = (w >> 2) * 64;

    float acc[2][8][4];
    #pragma unroll
    for (int i = 0; i < 2; i++)
        #pragma unroll
        for (int j = 0; j < 8; j++)
            #pragma unroll
            for (int q = 0; q < 4; q++) acc[i][j][q] = 0.f;

    const int ldRow = tid >> 3;
    const int ldCol = (tid & 7) * 4;

    float4 stA[4], stB[4];
    #pragma unroll
    for (int p = 0; p < 4; p++) {
        int row = ldRow + p * 32;
        stA[p] = *(const float4*)(Qb + (size_t)(mBase + row) * DIM + ldCol);
        stB[p] = *(const float4*)(W + (size_t)(nBase + row) * DIM2 + ldCol);
    }

    for (int k0 = 0; k0 < DIM2; k0 += BK) {
        #pragma unroll
        for (int p = 0; p < 4; p++) {
            int row = ldRow + p * 32;
            uint32_t* pa = &As[row * AS_STRIDE + ldCol];
            pa[0] = f2tf32(stA[p].x); pa[1] = f2tf32(stA[p].y);
            pa[2] = f2tf32(stA[p].z); pa[3] = f2tf32(stA[p].w);
            uint32_t* pb = &Bs[row * BS_STRIDE + ldCol];
            pb[0] = f2tf32(stB[p].x); pb[1] = f2tf32(stB[p].y);
            pb[2] = f2tf32(stB[p].z); pb[3] = f2tf32(stB[p].w);
        }
        __syncthreads();

        if (k0 + BK < DIM2) {
            int kn = k0 + BK;
            const float* Asrc = (kn < DIM) ? Qb : Cb;
            int kk = kn & (DIM - 1);
            #pragma unroll
            for (int p = 0; p < 4; p++) {
                int row = ldRow + p * 32;
                stA[p] = *(const float4*)(Asrc + (size_t)(mBase + row) * DIM + kk + ldCol);
                stB[p] = *(const float4*)(W + (size_t)(nBase + row) * DIM2 + kn + ldCol);
            }
        }

        #pragma unroll
        for (int kc = 0; kc < BK; kc += 8) {
            uint32_t af[2][4], bf[8][2];
            #pragma unroll
            for (int mi = 0; mi < 2; mi++) {
                int r = m0 + mi * 16 + (lane >> 2);
                int c = kc + (lane & 3);
                af[mi][0] = As[r * AS_STRIDE + c];
                af[mi][1] = As[(r + 8) * AS_STRIDE + c];
                af[mi][2] = As[r * AS_STRIDE + c + 4];
                af[mi][3] = As[(r + 8) * AS_STRIDE + c + 4];
            }
            #pragma unroll
            for (int nj = 0; nj < 8; nj++) {
                int r = n0 + nj * 8 + (lane >> 2);
                int c = kc + (lane & 3);
                bf[nj][0] = Bs[r * BS_STRIDE + c];
                bf[nj][1] = Bs[r * BS_STRIDE + c + 4];
            }
            #pragma unroll
            for (int mi = 0; mi < 2; mi++)
                #pragma unroll
                for (int nj = 0; nj < 8; nj++)
                    mma_tf32(acc[mi][nj], af[mi][0], af[mi][1], af[mi][2], af[mi][3],
                             bf[nj][0], bf[nj][1]);
        }
        __syncthreads();
    }

    #pragma unroll
    for (int mi = 0; mi < 2; mi++) {
        #pragma unroll
        for (int nj = 0; nj < 8; nj++) {
            int row = mBase + m0 + mi * 16 + (lane >> 2);
            int col = nBase + n0 + nj * 8 + (lane & 3) * 2;
            float b0 = bias[col], b1 = bias[col + 1];
            float mk0 = mask[(size_t)b * SQ + row];
            float mk1 = mask[(size_t)b * SQ + row + 8];
            float2 v0 = make_float2(tanhf(acc[mi][nj][0] + b0) * mk0,
                                    tanhf(acc[mi][nj][1] + b1) * mk0);
            float2 v1 = make_float2(tanhf(acc[mi][nj][2] + b0) * mk1,
                                    tanhf(acc[mi][nj][3] + b1) * mk1);
            *(float2*)(Ob + (size_t)row * DIM + col) = v0;
            *(float2*)(Ob + (size_t)(row + 8) * DIM + col) = v1;
        }
    }
}

// ---------------------------------------------------------------------------
extern "C" void kernel_launch(void* const* d_in, const int* in_sizes, int n_in,
                              void* d_out, int out_size)
{
    const float* Q    = (const float*)d_in[0];
    const float* E    = (const float*)d_in[1];
    const float* mask = (const float*)d_in[2];
    const float* W    = (const float*)d_in[3];
    const float* bias = (const float*)d_in[4];

    float* out = (float*)d_out;
    float* out_masked  = out;
    float* out_weights = out + (size_t)BATCH * SQ * DIM;

    float* ctx;
    cudaGetSymbolAddress((void**)&ctx, g_ctx);

    dim3 blk(256);
    dim3 grid(SK / BN, SQ / BM, BATCH);   // (4,4,32)

    gemm_scores_tc<<<grid, blk>>>(Q, E, out_weights);
    softmax_rows<<<BATCH * SQ, 256>>>(out_weights);
    gemm_ctx_tc<<<grid, blk>>>(out_weights, E, ctx);
    gemm_out_tc<<<grid, blk>>>(Q, W, bias, mask, out_masked);
}